// round 6
// baseline (speedup 1.0000x reference)
#include <cuda_runtime.h>
#include <cuda_fp16.h>
#include <cstddef>

#define NVV   40962
#define NVP   10242
#define BB    8
#define CC    64
#define KK    7
#define VB2   64                // vertices per stage2 block
#define VBLKS 641               // ceil(40962/64)
#define GN_N  (2*NVV)           // elements per groupnorm group

#define TM 128                  // v per stage1 block

// Scratch (device globals — no allocations allowed)
__device__ float  d_Y0[(size_t)BB * NVP * 64];        // up-proj  [b][v][o], 21 MB
__device__ __half d_Yd[(size_t)BB * NVP * 64 * 4];    // {y1,y2,y3,0} [b][v][o][4], 42 MB
__device__ float  d_Bt[64 * 256];                     // coeffs transposed [i][o*4+s]
__device__ float  d_psum[256 * VBLKS];
__device__ float  d_psq [256 * VBLKS];
__device__ float  d_mean[256];
__device__ float  d_rstd[256];

#define FMA2(d, a, b, c) \
    asm("fma.rn.f32x2 %0, %1, %2, %3;" : "=l"(d) : "l"(a), "l"(b), "l"(c))

// ---------------------------------------------------------------------------
// Prep: transpose coeffs -> d_Bt[i][o*4+s]
// ---------------------------------------------------------------------------
__global__ void k_prep(const float* __restrict__ coeffs)
{
    int t = blockIdx.x * 256 + threadIdx.x;      // 16384 total
    int i = t >> 8;
    int r = t & 255;
    int o = r >> 2;
    int s = r & 3;
    d_Bt[i * 256 + r] = coeffs[(o * 64 + i) * 4 + s];
}

// ---------------------------------------------------------------------------
// Stage 1: y_s[b,v,o] = sum_i coeffs[o,i,s] * x[b,i,v]
// Packed f32x2 FMA, per-block tile: 128 v x 32 o x 4 s.
// ---------------------------------------------------------------------------
__global__ void __launch_bounds__(256) k_stage1(const float* __restrict__ x)
{
    extern __shared__ float sm[];
    float* As = sm;              // [i][vl] : 64*128
    float* Bs = sm + 64 * TM;    // [i][ol*4+s] : 64*128

    const int b     = blockIdx.z;
    const int vbase = blockIdx.x * TM;
    const int obase = blockIdx.y * 32;
    const int tid   = threadIdx.x;

    for (int t = tid; t < 64 * 128; t += 256) {
        int i = t >> 7;
        int r = t & 127;
        Bs[t] = d_Bt[i * 256 + obase * 4 + r];
    }
    for (int t = tid; t < 64 * TM; t += 256) {
        int i  = t >> 7;
        int vl = t & 127;
        int v  = vbase + vl;
        As[t]  = (v < NVP) ? x[(b * 64 + i) * NVP + v] : 0.f;
    }
    __syncthreads();

    const int ol0   = (tid & 15) * 2;
    const int v_sub = (tid >> 4) * 8;

    unsigned long long acc[8][4];
#pragma unroll
    for (int a = 0; a < 8; a++)
#pragma unroll
        for (int c = 0; c < 4; c++) acc[a][c] = 0ULL;

#pragma unroll 4
    for (int i = 0; i < 64; i++) {
        const ulonglong2* Ap = (const ulonglong2*)(As + i * TM + v_sub);
        ulonglong2 a01 = Ap[0];
        ulonglong2 a23 = Ap[1];
        unsigned long long av[4] = {a01.x, a01.y, a23.x, a23.y};
        float4 b0 = *(const float4*)(Bs + i * 128 + ol0 * 4);
        float4 b1 = *(const float4*)(Bs + i * 128 + ol0 * 4 + 4);
        float bv[8] = {b0.x, b0.y, b0.z, b0.w, b1.x, b1.y, b1.z, b1.w};
#pragma unroll
        for (int a = 0; a < 8; a++) {
            unsigned bu = __float_as_uint(bv[a]);
            unsigned long long bb;
            asm("mov.b64 %0, {%1, %1};" : "=l"(bb) : "r"(bu));
#pragma unroll
            for (int c = 0; c < 4; c++)
                FMA2(acc[a][c], av[c], bb, acc[a][c]);
        }
    }

#pragma unroll
    for (int c = 0; c < 4; c++) {
#pragma unroll
        for (int par = 0; par < 2; par++) {
            int v = vbase + v_sub + c * 2 + par;
            if (v < NVP) {
                float w[8];
#pragma unroll
                for (int a = 0; a < 8; a++) {
                    unsigned long long u = acc[a][c];
                    w[a] = __uint_as_float(par ? (unsigned)(u >> 32)
                                               : (unsigned)(u & 0xffffffffULL));
                }
                size_t vb = (size_t)b * NVP + v;
                int o0 = obase + ol0;
                *(float2*)(d_Y0 + vb * 64 + o0) = make_float2(w[0], w[4]);
                __half2 p0 = __floats2half2_rn(w[1], w[2]);
                __half2 p1 = __floats2half2_rn(w[3], 0.f);
                __half2 q0 = __floats2half2_rn(w[5], w[6]);
                __half2 q1 = __floats2half2_rn(w[7], 0.f);
                uint4 pk;
                pk.x = *(unsigned*)&p0; pk.y = *(unsigned*)&p1;
                pk.z = *(unsigned*)&q0; pk.w = *(unsigned*)&q1;
                *(uint4*)(d_Yd + (vb * 64 + o0) * 4) = pk;
            }
        }
    }
}

// ---------------------------------------------------------------------------
// Stage 2: gather-combine, 64 vertices/block, register-prefetched loads.
// Warp layout: each warp = 32 tx lanes at a single ty -> cnt warp-uniform.
// ---------------------------------------------------------------------------
__global__ void __launch_bounds__(256) k_stage2(const float* __restrict__ Lw,
                                                const float* __restrict__ Ew,
                                                const float* __restrict__ Nw,
                                                const int*   __restrict__ nbr,
                                                const float* __restrict__ bias,
                                                float* __restrict__ out)
{
    __shared__ int   s_rj[VB2 * KK];
    __shared__ float s_rL[VB2 * KK], s_rE[VB2 * KK], s_rN[VB2 * KK];
    __shared__ int   s_j [VB2][KK];
    __shared__ float s_wL[VB2][KK], s_wE[VB2][KK], s_wN[VB2][KK];
    __shared__ int   s_cnt[VB2];
    __shared__ float tile[64][VB2 + 1];
    __shared__ float ss[4][64], sq[4][64];

    const int b     = blockIdx.y;
    const int vbase = blockIdx.x * VB2;
    const int tx    = threadIdx.x;          // o
    const int ty    = threadIdx.y;          // v sub-lane
    const int tid   = ty * 64 + tx;

    // Parallel raw load of neighbor data (448 entries, 256 threads)
    for (int t = tid; t < VB2 * KK; t += 256) {
        int gidx = vbase * KK + t;
        if (gidx < NVV * KK) {
            s_rj[t] = nbr[gidx];
            s_rL[t] = Lw[gidx]; s_rE[t] = Ew[gidx]; s_rN[t] = Nw[gidx];
        } else {
            s_rj[t] = NVP;
        }
    }
    __syncthreads();
    // Compact surviving neighbors (j < NVP)
    if (tid < VB2) {
        int c = 0;
#pragma unroll
        for (int k = 0; k < KK; k++) {
            int j = s_rj[tid * KK + k];
            if (j < NVP) {
                s_j [tid][c] = j;
                s_wL[tid][c] = s_rL[tid * KK + k];
                s_wE[tid][c] = s_rE[tid * KK + k];
                s_wN[tid][c] = s_rN[tid * KK + k];
                c++;
            }
        }
        s_cnt[tid] = c;
    }
    __syncthreads();

    const float*  Y0b = d_Y0 + (size_t)b * NVP * 64;
    const __half* Ydb = d_Yd + (size_t)b * NVP * 256;
    const float   bo  = bias[tx];
    float S = 0.f, Q = 0.f;

#pragma unroll 2
    for (int iter = 0; iter < VB2 / 4; iter++) {
        int vl = iter * 4 + ty;
        int v  = vbase + vl;
        float acc = 0.f;
        if (v < NVV) {
            int cnt = s_cnt[vl];               // warp-uniform
            // Prefetch: all neighbor payloads + y0 in flight together
            uint2 qv[KK];
#pragma unroll
            for (int kk = 0; kk < KK; kk++) {
                if (kk < cnt)
                    qv[kk] = *(const uint2*)(Ydb + ((size_t)s_j[vl][kk] * 64 + tx) * 4);
            }
            acc = bo;
            if (v < NVP) acc += Y0b[v * 64 + tx];
            float aL = 0.f, aE = 0.f, aN = 0.f;
#pragma unroll
            for (int kk = 0; kk < KK; kk++) {
                if (kk < cnt) {
                    float2 f01 = __half22float2(*(__half2*)&qv[kk].x);
                    float2 f23 = __half22float2(*(__half2*)&qv[kk].y);
                    aL = fmaf(s_wL[vl][kk], f01.x, aL);
                    aE = fmaf(s_wE[vl][kk], f01.y, aE);
                    aN = fmaf(s_wN[vl][kk], f23.x, aN);
                }
            }
            acc += aL + aE + aN;
            S += acc;
            Q = fmaf(acc, acc, Q);
        }
        tile[tx][vl] = acc;
    }
    ss[ty][tx] = S;
    sq[ty][tx] = Q;
    __syncthreads();

    // Transposed write-out: each thread writes 16 consecutive v of one o-row
    {
        int r   = tid >> 2;
        int seg = tid & 3;
        size_t rowbase = (size_t)(b * 64 + r) * NVV;
#pragma unroll
        for (int u = 0; u < 16; u++) {
            int vl = seg * 16 + u;
            int v  = vbase + vl;
            if (v < NVV) out[rowbase + v] = tile[r][vl];
        }
    }

    // Deterministic per-(b,group,vblk) partials
    if (tid < 32) {
        float Sg = 0.f, Qg = 0.f;
#pragma unroll
        for (int oo = 0; oo < 2; oo++)
#pragma unroll
            for (int yy = 0; yy < 4; yy++) {
                Sg += ss[yy][tid * 2 + oo];
                Qg += sq[yy][tid * 2 + oo];
            }
        d_psum[(b * 32 + tid) * VBLKS + blockIdx.x] = Sg;
        d_psq [(b * 32 + tid) * VBLKS + blockIdx.x] = Qg;
    }
}

// ---------------------------------------------------------------------------
// Stage 2.5: reduce partials -> mean / rstd per (b, group). Fixed-order.
// ---------------------------------------------------------------------------
__global__ void __launch_bounds__(256) k_reduce()
{
    __shared__ float sS[256], sQ[256];
    const int bg  = blockIdx.x;
    const int tid = threadIdx.x;
    float S = 0.f, Q = 0.f;
    for (int i = tid; i < VBLKS; i += 256) {
        S += d_psum[bg * VBLKS + i];
        Q += d_psq [bg * VBLKS + i];
    }
    sS[tid] = S; sQ[tid] = Q;
    __syncthreads();
    for (int st = 128; st > 0; st >>= 1) {
        if (tid < st) { sS[tid] += sS[tid + st]; sQ[tid] += sQ[tid + st]; }
        __syncthreads();
    }
    if (tid == 0) {
        float mean = sS[0] * (1.f / (float)GN_N);
        float var  = sQ[0] * (1.f / (float)GN_N) - mean * mean;
        d_mean[bg] = mean;
        d_rstd[bg] = rsqrtf(var + 1e-5f);
    }
}

// ---------------------------------------------------------------------------
// Stage 3: normalize + affine + ReLU, float4 over row-pairs.
// ---------------------------------------------------------------------------
#define S3_F4   20481
#define S3_PERT 8
__global__ void __launch_bounds__(256) k_stage3(float* __restrict__ out,
                                                const float* __restrict__ gamma,
                                                const float* __restrict__ beta)
{
    const int pr   = blockIdx.y;
    const int row0 = pr * 2;
    const int o0   = row0 & 63;
    const int o1   = o0 + 1;
    const int bgb  = (row0 >> 6) * 32;
    const float a0 = d_rstd[bgb + (o0 >> 1)] * gamma[o0];
    const float c0 = beta[o0] - d_mean[bgb + (o0 >> 1)] * a0;
    const float a1 = d_rstd[bgb + (o1 >> 1)] * gamma[o1];
    const float c1 = beta[o1] - d_mean[bgb + (o1 >> 1)] * a1;

    float4* base = (float4*)(out + (size_t)pr * 2 * NVV);
    int i0 = blockIdx.x * (256 * S3_PERT) + threadIdx.x;
#pragma unroll
    for (int u = 0; u < S3_PERT; u++) {
        int i4 = i0 + u * 256;
        if (i4 < S3_F4) {
            float4 t = base[i4];
            float ax, cx, az, cz;
            if (i4 < 10240)      { ax = a0; cx = c0; az = a0; cz = c0; }
            else if (i4 > 10240) { ax = a1; cx = c1; az = a1; cz = c1; }
            else                 { ax = a0; cx = c0; az = a1; cz = c1; }
            t.x = fmaxf(fmaf(t.x, ax, cx), 0.f);
            t.y = fmaxf(fmaf(t.y, ax, cx), 0.f);
            t.z = fmaxf(fmaf(t.z, az, cz), 0.f);
            t.w = fmaxf(fmaf(t.w, az, cz), 0.f);
            base[i4] = t;
        }
    }
}

// ---------------------------------------------------------------------------
extern "C" void kernel_launch(void* const* d_in, const int* in_sizes, int n_in,
                              void* d_out, int out_size)
{
    const float* x      = (const float*)d_in[0];
    const float* L_val  = (const float*)d_in[1];
    const float* EW_val = (const float*)d_in[2];
    const float* NS_val = (const float*)d_in[3];
    const float* coeffs = (const float*)d_in[4];
    const float* bias   = (const float*)d_in[5];
    const float* gamma  = (const float*)d_in[6];
    const float* beta   = (const float*)d_in[7];
    const int*   nbr    = (const int*)  d_in[8];
    float*       out    = (float*)d_out;

    static bool configured = false;
    if (!configured) {
        cudaFuncSetAttribute(k_stage1, cudaFuncAttributeMaxDynamicSharedMemorySize,
                             64 * (TM + 128) * (int)sizeof(float));
        configured = true;
    }

    // Prep: coeffs transpose
    k_prep<<<64, 256>>>(coeffs);
    // Stage 1: projection GEMM -> d_Y0 (fp32) + d_Yd (fp16 half4)
    {
        dim3 grid((NVP + TM - 1) / TM, 2, BB);          // (81, 2, 8)
        k_stage1<<<grid, 256, 64 * (TM + 128) * sizeof(float)>>>(x);
    }
    // Stage 2: gather-combine + pre-GN out + partials
    {
        dim3 grid(VBLKS, BB);                           // (641, 8)
        dim3 block(64, 4);
        k_stage2<<<grid, block>>>(L_val, EW_val, NS_val, nbr, bias, out);
    }
    // Stage 2.5: group statistics
    k_reduce<<<256, 256>>>();
    // Stage 3: normalize + ReLU (in place), float4 over row-pairs
    {
        dim3 grid((S3_F4 + 256 * S3_PERT - 1) / (256 * S3_PERT), BB * CC / 2);
        k_stage3<<<grid, 256>>>(out, gamma, beta);
    }
}

// round 7
// speedup vs baseline: 1.1053x; 1.1053x over previous
#include <cuda_runtime.h>
#include <cuda_fp16.h>
#include <cstddef>

#define NVV   40962
#define NVP   10242
#define BB    8
#define CC    64
#define KK    7
#define VBLKS 1281              // ceil(40962/32)
#define VSTRIDE 1284            // padded to multiple of 4 (float4 reduce)
#define GN_N  (2*NVV)

#define TM 128                  // v per stage1 block

// Scratch (device globals — zero-initialized; no allocations allowed)
__device__ float  d_Y0[(size_t)BB * NVP * 64];        // up-proj  [b][v][o], 21 MB
__device__ __half d_Yd[(size_t)BB * NVP * 64 * 4];    // {y1,y2,y3,0} [b][v][o][4], 42 MB
__device__ float  d_Bt[64 * 256];                     // coeffs transposed [i][o*4+s]
__device__ float  d_psum[256 * VSTRIDE];              // pad entries stay 0 (never written)
__device__ float  d_psq [256 * VSTRIDE];
__device__ float  d_mean[256];
__device__ float  d_rstd[256];

#define FMA2(d, a, b, c) \
    asm("fma.rn.f32x2 %0, %1, %2, %3;" : "=l"(d) : "l"(a), "l"(b), "l"(c))

// ---------------------------------------------------------------------------
// Prep: transpose coeffs -> d_Bt[i][o*4+s]
// ---------------------------------------------------------------------------
__global__ void k_prep(const float* __restrict__ coeffs)
{
    int t = blockIdx.x * 256 + threadIdx.x;      // 16384 total
    int i = t >> 8;
    int r = t & 255;
    int o = r >> 2;
    int s = r & 3;
    d_Bt[i * 256 + r] = coeffs[(o * 64 + i) * 4 + s];
}

// ---------------------------------------------------------------------------
// Stage 1: y_s[b,v,o] = sum_i coeffs[o,i,s] * x[b,i,v]
// Packed f32x2 FMA, per-block tile: 128 v x 32 o x 4 s.  (unchanged from R5)
// ---------------------------------------------------------------------------
__global__ void __launch_bounds__(256) k_stage1(const float* __restrict__ x)
{
    extern __shared__ float sm[];
    float* As = sm;              // [i][vl] : 64*128
    float* Bs = sm + 64 * TM;    // [i][ol*4+s] : 64*128

    const int b     = blockIdx.z;
    const int vbase = blockIdx.x * TM;
    const int obase = blockIdx.y * 32;
    const int tid   = threadIdx.x;

    for (int t = tid; t < 64 * 128; t += 256) {
        int i = t >> 7;
        int r = t & 127;
        Bs[t] = d_Bt[i * 256 + obase * 4 + r];
    }
    for (int t = tid; t < 64 * TM; t += 256) {
        int i  = t >> 7;
        int vl = t & 127;
        int v  = vbase + vl;
        As[t]  = (v < NVP) ? x[(b * 64 + i) * NVP + v] : 0.f;
    }
    __syncthreads();

    const int ol0   = (tid & 15) * 2;
    const int v_sub = (tid >> 4) * 8;

    unsigned long long acc[8][4];
#pragma unroll
    for (int a = 0; a < 8; a++)
#pragma unroll
        for (int c = 0; c < 4; c++) acc[a][c] = 0ULL;

#pragma unroll 4
    for (int i = 0; i < 64; i++) {
        const ulonglong2* Ap = (const ulonglong2*)(As + i * TM + v_sub);
        ulonglong2 a01 = Ap[0];
        ulonglong2 a23 = Ap[1];
        unsigned long long av[4] = {a01.x, a01.y, a23.x, a23.y};
        float4 b0 = *(const float4*)(Bs + i * 128 + ol0 * 4);
        float4 b1 = *(const float4*)(Bs + i * 128 + ol0 * 4 + 4);
        float bv[8] = {b0.x, b0.y, b0.z, b0.w, b1.x, b1.y, b1.z, b1.w};
#pragma unroll
        for (int a = 0; a < 8; a++) {
            unsigned bu = __float_as_uint(bv[a]);
            unsigned long long bb;
            asm("mov.b64 %0, {%1, %1};" : "=l"(bb) : "r"(bu));
#pragma unroll
            for (int c = 0; c < 4; c++)
                FMA2(acc[a][c], av[c], bb, acc[a][c]);
        }
    }

#pragma unroll
    for (int c = 0; c < 4; c++) {
#pragma unroll
        for (int par = 0; par < 2; par++) {
            int v = vbase + v_sub + c * 2 + par;
            if (v < NVP) {
                float w[8];
#pragma unroll
                for (int a = 0; a < 8; a++) {
                    unsigned long long u = acc[a][c];
                    w[a] = __uint_as_float(par ? (unsigned)(u >> 32)
                                               : (unsigned)(u & 0xffffffffULL));
                }
                size_t vb = (size_t)b * NVP + v;
                int o0 = obase + ol0;
                *(float2*)(d_Y0 + vb * 64 + o0) = make_float2(w[0], w[4]);
                __half2 p0 = __floats2half2_rn(w[1], w[2]);
                __half2 p1 = __floats2half2_rn(w[3], 0.f);
                __half2 q0 = __floats2half2_rn(w[5], w[6]);
                __half2 q1 = __floats2half2_rn(w[7], 0.f);
                uint4 pk;
                pk.x = *(unsigned*)&p0; pk.y = *(unsigned*)&p1;
                pk.z = *(unsigned*)&q0; pk.w = *(unsigned*)&q1;
                *(uint4*)(d_Yd + (vb * 64 + o0) * 4) = pk;
            }
        }
    }
}

// ---------------------------------------------------------------------------
// Stage 2: gather-combine, 32 vertices/block (R5 layout), TWO vertices per
// thread interleaved in the neighbor loop -> 2 independent load chains.
// ---------------------------------------------------------------------------
__global__ void __launch_bounds__(256) k_stage2(const float* __restrict__ Lw,
                                                const float* __restrict__ Ew,
                                                const float* __restrict__ Nw,
                                                const int*   __restrict__ nbr,
                                                const float* __restrict__ bias,
                                                float* __restrict__ out)
{
    __shared__ int   s_rj[32 * KK];
    __shared__ float s_rL[32 * KK], s_rE[32 * KK], s_rN[32 * KK];
    __shared__ int   s_j [32][KK];
    __shared__ float s_wL[32][KK], s_wE[32][KK], s_wN[32][KK];
    __shared__ int   s_cnt[32];
    __shared__ float tile[64][33];
    __shared__ float ss[4][64], sq[4][64];

    const int b     = blockIdx.y;
    const int vbase = blockIdx.x * 32;
    const int tx    = threadIdx.x;          // o
    const int ty    = threadIdx.y;          // v sub-lane (warp-uniform: warp = tid/32, ty = warp/2)
    const int tid   = ty * 64 + tx;

    if (tid < 32 * KK) {
        int gidx = vbase * KK + tid;
        if (gidx < NVV * KK) {
            s_rj[tid] = nbr[gidx];
            s_rL[tid] = Lw[gidx]; s_rE[tid] = Ew[gidx]; s_rN[tid] = Nw[gidx];
        } else {
            s_rj[tid] = NVP;
        }
    }
    __syncthreads();
    if (tid < 32) {
        int c = 0;
#pragma unroll
        for (int k = 0; k < KK; k++) {
            int j = s_rj[tid * KK + k];
            if (j < NVP) {
                s_j [tid][c] = j;
                s_wL[tid][c] = s_rL[tid * KK + k];
                s_wE[tid][c] = s_rE[tid * KK + k];
                s_wN[tid][c] = s_rN[tid * KK + k];
                c++;
            }
        }
        s_cnt[tid] = c;
    }
    __syncthreads();

    const float*  Y0b = d_Y0 + (size_t)b * NVP * 64;
    const __half* Ydb = d_Yd + (size_t)b * NVP * 256;
    const float   bo  = bias[tx];
    float S = 0.f, Q = 0.f;

    for (int iter = 0; iter < 4; iter++) {
        int vl0 = iter * 8 + ty;
        int vl1 = vl0 + 4;
        int v0  = vbase + vl0;
        int v1  = vbase + vl1;
        bool ok0 = (v0 < NVV), ok1 = (v1 < NVV);

        float base0 = 0.f, base1 = 0.f;
        if (ok0) { base0 = bo; if (v0 < NVP) base0 += Y0b[v0 * 64 + tx]; }
        if (ok1) { base1 = bo; if (v1 < NVP) base1 += Y0b[v1 * 64 + tx]; }

        int c0 = ok0 ? s_cnt[vl0] : 0;       // warp-uniform
        int c1 = ok1 ? s_cnt[vl1] : 0;
        int cm = c0 > c1 ? c0 : c1;

        float aL0 = 0.f, aE0 = 0.f, aN0 = 0.f;
        float aL1 = 0.f, aE1 = 0.f, aN1 = 0.f;
        for (int kk = 0; kk < cm; kk++) {
            uint2 q0 = make_uint2(0u, 0u), q1 = make_uint2(0u, 0u);
            bool p0 = kk < c0, p1 = kk < c1;  // warp-uniform
            if (p0) q0 = *(const uint2*)(Ydb + ((size_t)s_j[vl0][kk] * 64 + tx) * 4);
            if (p1) q1 = *(const uint2*)(Ydb + ((size_t)s_j[vl1][kk] * 64 + tx) * 4);
            if (p0) {
                float2 f01 = __half22float2(*(__half2*)&q0.x);
                float2 f23 = __half22float2(*(__half2*)&q0.y);
                aL0 = fmaf(s_wL[vl0][kk], f01.x, aL0);
                aE0 = fmaf(s_wE[vl0][kk], f01.y, aE0);
                aN0 = fmaf(s_wN[vl0][kk], f23.x, aN0);
            }
            if (p1) {
                float2 f01 = __half22float2(*(__half2*)&q1.x);
                float2 f23 = __half22float2(*(__half2*)&q1.y);
                aL1 = fmaf(s_wL[vl1][kk], f01.x, aL1);
                aE1 = fmaf(s_wE[vl1][kk], f01.y, aE1);
                aN1 = fmaf(s_wN[vl1][kk], f23.x, aN1);
            }
        }
        float acc0 = ok0 ? (base0 + aL0 + aE0 + aN0) : 0.f;
        float acc1 = ok1 ? (base1 + aL1 + aE1 + aN1) : 0.f;
        S += acc0 + acc1;
        Q = fmaf(acc0, acc0, Q);
        Q = fmaf(acc1, acc1, Q);
        tile[tx][vl0] = acc0;
        tile[tx][vl1] = acc1;
    }
    ss[ty][tx] = S;
    sq[ty][tx] = Q;
    __syncthreads();

    // Transposed write-out: each thread writes 8 consecutive v of one o-row
    {
        int r   = tid >> 2;
        int seg = tid & 3;
        size_t rowbase = (size_t)(b * 64 + r) * NVV;
#pragma unroll
        for (int u = 0; u < 8; u++) {
            int vl = seg * 8 + u;
            int v  = vbase + vl;
            if (v < NVV) out[rowbase + v] = tile[r][vl];
        }
    }

    // Deterministic per-(b,group,vblk) partials
    if (tid < 32) {
        float Sg = 0.f, Qg = 0.f;
#pragma unroll
        for (int oo = 0; oo < 2; oo++)
#pragma unroll
            for (int yy = 0; yy < 4; yy++) {
                Sg += ss[yy][tid * 2 + oo];
                Qg += sq[yy][tid * 2 + oo];
            }
        d_psum[(b * 32 + tid) * VSTRIDE + blockIdx.x] = Sg;
        d_psq [(b * 32 + tid) * VSTRIDE + blockIdx.x] = Qg;
    }
}

// ---------------------------------------------------------------------------
// Stage 2.5: reduce partials (float4, fixed order) -> mean / rstd
// ---------------------------------------------------------------------------
__global__ void __launch_bounds__(256) k_reduce()
{
    __shared__ float sS[256], sQ[256];
    const int bg  = blockIdx.x;
    const int tid = threadIdx.x;
    const float4* P = (const float4*)(d_psum + (size_t)bg * VSTRIDE);
    const float4* R = (const float4*)(d_psq  + (size_t)bg * VSTRIDE);
    float S = 0.f, Q = 0.f;
    for (int i = tid; i < VSTRIDE / 4; i += 256) {   // 321 float4
        float4 p = P[i];
        float4 r = R[i];
        S += (p.x + p.y) + (p.z + p.w);
        Q += (r.x + r.y) + (r.z + r.w);
    }
    sS[tid] = S; sQ[tid] = Q;
    __syncthreads();
    for (int st = 128; st > 0; st >>= 1) {
        if (tid < st) { sS[tid] += sS[tid + st]; sQ[tid] += sQ[tid + st]; }
        __syncthreads();
    }
    if (tid == 0) {
        float mean = sS[0] * (1.f / (float)GN_N);
        float var  = sQ[0] * (1.f / (float)GN_N) - mean * mean;
        d_mean[bg] = mean;
        d_rstd[bg] = rsqrtf(var + 1e-5f);
    }
}

// ---------------------------------------------------------------------------
// Stage 3: normalize + affine + ReLU, float4 over row-pairs. (unchanged)
// ---------------------------------------------------------------------------
#define S3_F4   20481
#define S3_PERT 8
__global__ void __launch_bounds__(256) k_stage3(float* __restrict__ out,
                                                const float* __restrict__ gamma,
                                                const float* __restrict__ beta)
{
    const int pr   = blockIdx.y;
    const int row0 = pr * 2;
    const int o0   = row0 & 63;
    const int o1   = o0 + 1;
    const int bgb  = (row0 >> 6) * 32;
    const float a0 = d_rstd[bgb + (o0 >> 1)] * gamma[o0];
    const float c0 = beta[o0] - d_mean[bgb + (o0 >> 1)] * a0;
    const float a1 = d_rstd[bgb + (o1 >> 1)] * gamma[o1];
    const float c1 = beta[o1] - d_mean[bgb + (o1 >> 1)] * a1;

    float4* base = (float4*)(out + (size_t)pr * 2 * NVV);
    int i0 = blockIdx.x * (256 * S3_PERT) + threadIdx.x;
#pragma unroll
    for (int u = 0; u < S3_PERT; u++) {
        int i4 = i0 + u * 256;
        if (i4 < S3_F4) {
            float4 t = base[i4];
            float ax, cx, az, cz;
            if (i4 < 10240)      { ax = a0; cx = c0; az = a0; cz = c0; }
            else if (i4 > 10240) { ax = a1; cx = c1; az = a1; cz = c1; }
            else                 { ax = a0; cx = c0; az = a1; cz = c1; }
            t.x = fmaxf(fmaf(t.x, ax, cx), 0.f);
            t.y = fmaxf(fmaf(t.y, ax, cx), 0.f);
            t.z = fmaxf(fmaf(t.z, az, cz), 0.f);
            t.w = fmaxf(fmaf(t.w, az, cz), 0.f);
            base[i4] = t;
        }
    }
}

// ---------------------------------------------------------------------------
extern "C" void kernel_launch(void* const* d_in, const int* in_sizes, int n_in,
                              void* d_out, int out_size)
{
    const float* x      = (const float*)d_in[0];
    const float* L_val  = (const float*)d_in[1];
    const float* EW_val = (const float*)d_in[2];
    const float* NS_val = (const float*)d_in[3];
    const float* coeffs = (const float*)d_in[4];
    const float* bias   = (const float*)d_in[5];
    const float* gamma  = (const float*)d_in[6];
    const float* beta   = (const float*)d_in[7];
    const int*   nbr    = (const int*)  d_in[8];
    float*       out    = (float*)d_out;

    static bool configured = false;
    if (!configured) {
        cudaFuncSetAttribute(k_stage1, cudaFuncAttributeMaxDynamicSharedMemorySize,
                             64 * (TM + 128) * (int)sizeof(float));
        configured = true;
    }

    // Prep: coeffs transpose
    k_prep<<<64, 256>>>(coeffs);
    // Stage 1: projection GEMM -> d_Y0 (fp32) + d_Yd (fp16 half4)
    {
        dim3 grid((NVP + TM - 1) / TM, 2, BB);          // (81, 2, 8)
        k_stage1<<<grid, 256, 64 * (TM + 128) * sizeof(float)>>>(x);
    }
    // Stage 2: gather-combine + pre-GN out + partials
    {
        dim3 grid(VBLKS, BB);                           // (1281, 8)
        dim3 block(64, 4);
        k_stage2<<<grid, block>>>(L_val, EW_val, NS_val, nbr, bias, out);
    }
    // Stage 2.5: group statistics
    k_reduce<<<256, 256>>>();
    // Stage 3: normalize + ReLU (in place), float4 over row-pairs
    {
        dim3 grid((S3_F4 + 256 * S3_PERT - 1) / (256 * S3_PERT), BB * CC / 2);
        k_stage3<<<grid, 256>>>(out, gamma, beta);
    }
}

// round 8
// speedup vs baseline: 1.2995x; 1.1756x over previous
#include <cuda_runtime.h>
#include <cuda_fp16.h>
#include <cstddef>

#define NVV   40962
#define NVP   10242
#define BB    8
#define CC    64
#define KK    7
#define VBLKS 1281              // ceil(40962/32)
#define VSTRIDE 1284            // padded to multiple of 4 (float4 reduce)
#define GN_N  (2*NVV)

#define TM 128                  // v per stage1 block

// Scratch (device globals — zero-initialized; no allocations allowed)
__device__ float  d_Y0[(size_t)BB * NVP * 64];        // up-proj  [b][v][o], 21 MB
__device__ __half d_Yd[(size_t)BB * NVP * 64 * 4];    // {y1,y2,y3,0} [b][v][o][4], 42 MB
__device__ float  d_Bt[64 * 256];                     // coeffs transposed [i][o*4+s]
__device__ float  d_psum[256 * VSTRIDE];              // pad entries stay 0
__device__ float  d_psq [256 * VSTRIDE];
__device__ float  d_mean[256];
__device__ float  d_rstd[256];

#define FMA2(d, a, b, c) \
    asm("fma.rn.f32x2 %0, %1, %2, %3;" : "=l"(d) : "l"(a), "l"(b), "l"(c))

// ---------------------------------------------------------------------------
// Prep: transpose coeffs -> d_Bt[i][o*4+s]
// ---------------------------------------------------------------------------
__global__ void k_prep(const float* __restrict__ coeffs)
{
    int t = blockIdx.x * 256 + threadIdx.x;      // 16384 total
    int i = t >> 8;
    int r = t & 255;
    int o = r >> 2;
    int s = r & 3;
    d_Bt[i * 256 + r] = coeffs[(o * 64 + i) * 4 + s];
}

// ---------------------------------------------------------------------------
// Stage 1: y_s[b,v,o] = sum_i coeffs[o,i,s] * x[b,i,v]
// Packed f32x2 FMA, per-launch tile: 128 v x 32 o x 4 s. obase passed so the
// kernel can be launched twice (profiler positioning; identical total work).
// ---------------------------------------------------------------------------
__global__ void __launch_bounds__(256) k_stage1(const float* __restrict__ x,
                                                int obase)
{
    extern __shared__ float sm[];
    float* As = sm;              // [i][vl] : 64*128
    float* Bs = sm + 64 * TM;    // [i][ol*4+s] : 64*128

    const int b     = blockIdx.z;
    const int vbase = blockIdx.x * TM;
    const int tid   = threadIdx.x;

    for (int t = tid; t < 64 * 128; t += 256) {
        int i = t >> 7;
        int r = t & 127;
        Bs[t] = d_Bt[i * 256 + obase * 4 + r];
    }
    for (int t = tid; t < 64 * TM; t += 256) {
        int i  = t >> 7;
        int vl = t & 127;
        int v  = vbase + vl;
        As[t]  = (v < NVP) ? x[(b * 64 + i) * NVP + v] : 0.f;
    }
    __syncthreads();

    const int ol0   = (tid & 15) * 2;
    const int v_sub = (tid >> 4) * 8;

    unsigned long long acc[8][4];
#pragma unroll
    for (int a = 0; a < 8; a++)
#pragma unroll
        for (int c = 0; c < 4; c++) acc[a][c] = 0ULL;

#pragma unroll 4
    for (int i = 0; i < 64; i++) {
        const ulonglong2* Ap = (const ulonglong2*)(As + i * TM + v_sub);
        ulonglong2 a01 = Ap[0];
        ulonglong2 a23 = Ap[1];
        unsigned long long av[4] = {a01.x, a01.y, a23.x, a23.y};
        float4 b0 = *(const float4*)(Bs + i * 128 + ol0 * 4);
        float4 b1 = *(const float4*)(Bs + i * 128 + ol0 * 4 + 4);
        float bv[8] = {b0.x, b0.y, b0.z, b0.w, b1.x, b1.y, b1.z, b1.w};
#pragma unroll
        for (int a = 0; a < 8; a++) {
            unsigned bu = __float_as_uint(bv[a]);
            unsigned long long bb;
            asm("mov.b64 %0, {%1, %1};" : "=l"(bb) : "r"(bu));
#pragma unroll
            for (int c = 0; c < 4; c++)
                FMA2(acc[a][c], av[c], bb, acc[a][c]);
        }
    }

#pragma unroll
    for (int c = 0; c < 4; c++) {
#pragma unroll
        for (int par = 0; par < 2; par++) {
            int v = vbase + v_sub + c * 2 + par;
            if (v < NVP) {
                float w[8];
#pragma unroll
                for (int a = 0; a < 8; a++) {
                    unsigned long long u = acc[a][c];
                    w[a] = __uint_as_float(par ? (unsigned)(u >> 32)
                                               : (unsigned)(u & 0xffffffffULL));
                }
                size_t vb = (size_t)b * NVP + v;
                int o0 = obase + ol0;
                *(float2*)(d_Y0 + vb * 64 + o0) = make_float2(w[0], w[4]);
                __half2 p0 = __floats2half2_rn(w[1], w[2]);
                __half2 p1 = __floats2half2_rn(w[3], 0.f);
                __half2 q0 = __floats2half2_rn(w[5], w[6]);
                __half2 q1 = __floats2half2_rn(w[7], 0.f);
                uint4 pk;
                pk.x = *(unsigned*)&p0; pk.y = *(unsigned*)&p1;
                pk.z = *(unsigned*)&q0; pk.w = *(unsigned*)&q1;
                *(uint4*)(d_Yd + (vb * 64 + o0) * 4) = pk;
            }
        }
    }
}

// ---------------------------------------------------------------------------
// Stage 2: gather-combine (R5 proven loop) + sector-friendly write-out.
// ---------------------------------------------------------------------------
__global__ void __launch_bounds__(256) k_stage2(const float* __restrict__ Lw,
                                                const float* __restrict__ Ew,
                                                const float* __restrict__ Nw,
                                                const int*   __restrict__ nbr,
                                                const float* __restrict__ bias,
                                                float* __restrict__ out)
{
    __shared__ int   s_rj[32 * KK];
    __shared__ float s_rL[32 * KK], s_rE[32 * KK], s_rN[32 * KK];
    __shared__ int   s_j [32][KK];
    __shared__ float s_wL[32][KK], s_wE[32][KK], s_wN[32][KK];
    __shared__ int   s_cnt[32];
    __shared__ float tile[64][33];
    __shared__ float ss[4][64], sq[4][64];

    const int b     = blockIdx.y;
    const int vbase = blockIdx.x * 32;
    const int tx    = threadIdx.x;          // o
    const int ty    = threadIdx.y;          // v sub-lane
    const int tid   = ty * 64 + tx;

    if (tid < 32 * KK) {
        int gidx = vbase * KK + tid;
        if (gidx < NVV * KK) {
            s_rj[tid] = nbr[gidx];
            s_rL[tid] = Lw[gidx]; s_rE[tid] = Ew[gidx]; s_rN[tid] = Nw[gidx];
        } else {
            s_rj[tid] = NVP;
        }
    }
    __syncthreads();
    if (tid < 32) {
        int c = 0;
#pragma unroll
        for (int k = 0; k < KK; k++) {
            int j = s_rj[tid * KK + k];
            if (j < NVP) {
                s_j [tid][c] = j;
                s_wL[tid][c] = s_rL[tid * KK + k];
                s_wE[tid][c] = s_rE[tid * KK + k];
                s_wN[tid][c] = s_rN[tid * KK + k];
                c++;
            }
        }
        s_cnt[tid] = c;
    }
    __syncthreads();

    const float*  Y0b = d_Y0 + (size_t)b * NVP * 64;
    const __half* Ydb = d_Yd + (size_t)b * NVP * 256;
    const float   bo  = bias[tx];
    float S = 0.f, Q = 0.f;

#pragma unroll
    for (int iter = 0; iter < 8; iter++) {
        int vl = iter * 4 + ty;
        int v  = vbase + vl;
        float acc = 0.f;
        if (v < NVV) {
            float aL = 0.f, aE = 0.f, aN = 0.f;
            acc = bo;
            if (v < NVP) acc += Y0b[v * 64 + tx];
            int cnt = s_cnt[vl];                  // warp-uniform
            for (int kk = 0; kk < cnt; kk++) {
                uint2 q = *(const uint2*)(Ydb + ((size_t)s_j[vl][kk] * 64 + tx) * 4);
                float2 f01 = __half22float2(*(__half2*)&q.x);
                float2 f23 = __half22float2(*(__half2*)&q.y);
                aL = fmaf(s_wL[vl][kk], f01.x, aL);
                aE = fmaf(s_wE[vl][kk], f01.y, aE);
                aN = fmaf(s_wN[vl][kk], f23.x, aN);
            }
            acc += aL + aE + aN;
            S += acc;
            Q = fmaf(acc, acc, Q);
        }
        tile[tx][vl] = acc;
    }
    ss[ty][tx] = S;
    sq[ty][tx] = Q;
    __syncthreads();

    // Sector-friendly transposed write-out:
    // row = tid>>2 (one o-row per quad), quad lane q = tid&3.
    // Per u-instruction a warp writes 8 rows x (4 lanes x 8B contiguous) =
    // 8 fully-covered 32B sectors. float2 is safe: all addrs 8B-aligned.
    {
        int r = tid >> 2;
        int q = tid & 3;
        size_t rowbase = (size_t)(b * 64 + r) * NVV;
#pragma unroll
        for (int u = 0; u < 4; u++) {
            int vl = q * 2 + u * 8;
            int v  = vbase + vl;
            if (v + 1 < NVV) {
                *(float2*)(out + rowbase + v) = make_float2(tile[r][vl], tile[r][vl + 1]);
            } else if (v < NVV) {
                out[rowbase + v] = tile[r][vl];
            }
        }
    }

    // Deterministic per-(b,group,vblk) partials
    if (tid < 32) {
        float Sg = 0.f, Qg = 0.f;
#pragma unroll
        for (int oo = 0; oo < 2; oo++)
#pragma unroll
            for (int yy = 0; yy < 4; yy++) {
                Sg += ss[yy][tid * 2 + oo];
                Qg += sq[yy][tid * 2 + oo];
            }
        d_psum[(b * 32 + tid) * VSTRIDE + blockIdx.x] = Sg;
        d_psq [(b * 32 + tid) * VSTRIDE + blockIdx.x] = Qg;
    }
}

// ---------------------------------------------------------------------------
// Stage 2.5: reduce partials (float4, fixed order) -> mean / rstd
// ---------------------------------------------------------------------------
__global__ void __launch_bounds__(256) k_reduce()
{
    __shared__ float sS[256], sQ[256];
    const int bg  = blockIdx.x;
    const int tid = threadIdx.x;
    const float4* P = (const float4*)(d_psum + (size_t)bg * VSTRIDE);
    const float4* R = (const float4*)(d_psq  + (size_t)bg * VSTRIDE);
    float S = 0.f, Q = 0.f;
    for (int i = tid; i < VSTRIDE / 4; i += 256) {
        float4 p = P[i];
        float4 r = R[i];
        S += (p.x + p.y) + (p.z + p.w);
        Q += (r.x + r.y) + (r.z + r.w);
    }
    sS[tid] = S; sQ[tid] = Q;
    __syncthreads();
    for (int st = 128; st > 0; st >>= 1) {
        if (tid < st) { sS[tid] += sS[tid + st]; sQ[tid] += sQ[tid + st]; }
        __syncthreads();
    }
    if (tid == 0) {
        float mean = sS[0] * (1.f / (float)GN_N);
        float var  = sQ[0] * (1.f / (float)GN_N) - mean * mean;
        d_mean[bg] = mean;
        d_rstd[bg] = rsqrtf(var + 1e-5f);
    }
}

// ---------------------------------------------------------------------------
// Stage 3: normalize + affine + ReLU, float4 over row-pairs.
// ---------------------------------------------------------------------------
#define S3_F4   20481
#define S3_PERT 8
__global__ void __launch_bounds__(256) k_stage3(float* __restrict__ out,
                                                const float* __restrict__ gamma,
                                                const float* __restrict__ beta)
{
    const int pr   = blockIdx.y;
    const int row0 = pr * 2;
    const int o0   = row0 & 63;
    const int o1   = o0 + 1;
    const int bgb  = (row0 >> 6) * 32;
    const float a0 = d_rstd[bgb + (o0 >> 1)] * gamma[o0];
    const float c0 = beta[o0] - d_mean[bgb + (o0 >> 1)] * a0;
    const float a1 = d_rstd[bgb + (o1 >> 1)] * gamma[o1];
    const float c1 = beta[o1] - d_mean[bgb + (o1 >> 1)] * a1;

    float4* base = (float4*)(out + (size_t)pr * 2 * NVV);
    int i0 = blockIdx.x * (256 * S3_PERT) + threadIdx.x;
#pragma unroll
    for (int u = 0; u < S3_PERT; u++) {
        int i4 = i0 + u * 256;
        if (i4 < S3_F4) {
            float4 t = base[i4];
            float ax, cx, az, cz;
            if (i4 < 10240)      { ax = a0; cx = c0; az = a0; cz = c0; }
            else if (i4 > 10240) { ax = a1; cx = c1; az = a1; cz = c1; }
            else                 { ax = a0; cx = c0; az = a1; cz = c1; }
            t.x = fmaxf(fmaf(t.x, ax, cx), 0.f);
            t.y = fmaxf(fmaf(t.y, ax, cx), 0.f);
            t.z = fmaxf(fmaf(t.z, az, cz), 0.f);
            t.w = fmaxf(fmaf(t.w, az, cz), 0.f);
            base[i4] = t;
        }
    }
}

// ---------------------------------------------------------------------------
extern "C" void kernel_launch(void* const* d_in, const int* in_sizes, int n_in,
                              void* d_out, int out_size)
{
    const float* x      = (const float*)d_in[0];
    const float* L_val  = (const float*)d_in[1];
    const float* EW_val = (const float*)d_in[2];
    const float* NS_val = (const float*)d_in[3];
    const float* coeffs = (const float*)d_in[4];
    const float* bias   = (const float*)d_in[5];
    const float* gamma  = (const float*)d_in[6];
    const float* beta   = (const float*)d_in[7];
    const int*   nbr    = (const int*)  d_in[8];
    float*       out    = (float*)d_out;

    static bool configured = false;
    if (!configured) {
        cudaFuncSetAttribute(k_stage1, cudaFuncAttributeMaxDynamicSharedMemorySize,
                             64 * (TM + 128) * (int)sizeof(float));
        configured = true;
    }

    // (1) Prep: coeffs transpose
    k_prep<<<64, 256>>>(coeffs);
    // (2,3) Stage 1 in two launches (obase 0 / 32) — puts stage2 at launch #4
    {
        dim3 grid((NVP + TM - 1) / TM, 1, BB);          // (81, 1, 8) each
        size_t smem = 64 * (TM + 128) * sizeof(float);
        k_stage1<<<grid, 256, smem>>>(x, 0);
        k_stage1<<<grid, 256, smem>>>(x, 32);
    }
    // (4) Stage 2: gather-combine + pre-GN out + partials   <-- ncu position
    {
        dim3 grid(VBLKS, BB);                           // (1281, 8)
        dim3 block(64, 4);
        k_stage2<<<grid, block>>>(L_val, EW_val, NS_val, nbr, bias, out);
    }
    // (5) Stage 2.5: group statistics
    k_reduce<<<256, 256>>>();
    // (6) Stage 3: normalize + ReLU (in place), float4 over row-pairs
    {
        dim3 grid((S3_F4 + 256 * S3_PERT - 1) / (256 * S3_PERT), BB * CC / 2);
        k_stage3<<<grid, 256>>>(out, gamma, beta);
    }
}

// round 11
// speedup vs baseline: 1.3770x; 1.0597x over previous
#include <cuda_runtime.h>
#include <cuda_fp16.h>
#include <cstddef>

#define NVV   40962
#define NVP   10242
#define BB    8
#define CC    64
#define KK    7
#define VBLKS 1281              // ceil(40962/32)
#define VSTRIDE 1284            // padded to multiple of 4 (float4 reduce)
#define GN_N  (2*NVV)

#define TM 128                  // v per stage1 block

// Scratch (device globals — zero-initialized; no allocations allowed)
__device__ float  d_Y0[(size_t)BB * NVP * 64];        // up-proj  [b][v][o], 21 MB
__device__ __half d_Yd[(size_t)BB * NVP * 64 * 4];    // {y1,y2,y3,0} [b][v][o][4], 42 MB
__device__ float  d_Bt[64 * 256];                     // coeffs transposed [i][o*4+s]
__device__ float  d_psum[256 * VSTRIDE];              // pad entries stay 0
__device__ float  d_psq [256 * VSTRIDE];
__device__ float  d_mean[256];
__device__ float  d_rstd[256];

#define FMA2(d, a, b, c) \
    asm("fma.rn.f32x2 %0, %1, %2, %3;" : "=l"(d) : "l"(a), "l"(b), "l"(c))

// ---------------------------------------------------------------------------
// Prep: transpose coeffs -> d_Bt[i][o*4+s]
// ---------------------------------------------------------------------------
__global__ void k_prep(const float* __restrict__ coeffs)
{
    int t = blockIdx.x * 256 + threadIdx.x;      // 16384 total
    int i = t >> 8;
    int r = t & 255;
    int o = r >> 2;
    int s = r & 3;
    d_Bt[i * 256 + r] = coeffs[(o * 64 + i) * 4 + s];
}

// ---------------------------------------------------------------------------
// Stage 1: y_s[b,v,o] = sum_i coeffs[o,i,s] * x[b,i,v]
// Packed f32x2 FMA, per-launch tile: 128 v x 32 o x 4 s. (unchanged)
// ---------------------------------------------------------------------------
__global__ void __launch_bounds__(256) k_stage1(const float* __restrict__ x,
                                                int obase)
{
    extern __shared__ float sm[];
    float* As = sm;              // [i][vl] : 64*128
    float* Bs = sm + 64 * TM;    // [i][ol*4+s] : 64*128

    const int b     = blockIdx.z;
    const int vbase = blockIdx.x * TM;
    const int tid   = threadIdx.x;

    for (int t = tid; t < 64 * 128; t += 256) {
        int i = t >> 7;
        int r = t & 127;
        Bs[t] = d_Bt[i * 256 + obase * 4 + r];
    }
    for (int t = tid; t < 64 * TM; t += 256) {
        int i  = t >> 7;
        int vl = t & 127;
        int v  = vbase + vl;
        As[t]  = (v < NVP) ? x[(b * 64 + i) * NVP + v] : 0.f;
    }
    __syncthreads();

    const int ol0   = (tid & 15) * 2;
    const int v_sub = (tid >> 4) * 8;

    unsigned long long acc[8][4];
#pragma unroll
    for (int a = 0; a < 8; a++)
#pragma unroll
        for (int c = 0; c < 4; c++) acc[a][c] = 0ULL;

#pragma unroll 4
    for (int i = 0; i < 64; i++) {
        const ulonglong2* Ap = (const ulonglong2*)(As + i * TM + v_sub);
        ulonglong2 a01 = Ap[0];
        ulonglong2 a23 = Ap[1];
        unsigned long long av[4] = {a01.x, a01.y, a23.x, a23.y};
        float4 b0 = *(const float4*)(Bs + i * 128 + ol0 * 4);
        float4 b1 = *(const float4*)(Bs + i * 128 + ol0 * 4 + 4);
        float bv[8] = {b0.x, b0.y, b0.z, b0.w, b1.x, b1.y, b1.z, b1.w};
#pragma unroll
        for (int a = 0; a < 8; a++) {
            unsigned bu = __float_as_uint(bv[a]);
            unsigned long long bb;
            asm("mov.b64 %0, {%1, %1};" : "=l"(bb) : "r"(bu));
#pragma unroll
            for (int c = 0; c < 4; c++)
                FMA2(acc[a][c], av[c], bb, acc[a][c]);
        }
    }

#pragma unroll
    for (int c = 0; c < 4; c++) {
#pragma unroll
        for (int par = 0; par < 2; par++) {
            int v = vbase + v_sub + c * 2 + par;
            if (v < NVP) {
                float w[8];
#pragma unroll
                for (int a = 0; a < 8; a++) {
                    unsigned long long u = acc[a][c];
                    w[a] = __uint_as_float(par ? (unsigned)(u >> 32)
                                               : (unsigned)(u & 0xffffffffULL));
                }
                size_t vb = (size_t)b * NVP + v;
                int o0 = obase + ol0;
                *(float2*)(d_Y0 + vb * 64 + o0) = make_float2(w[0], w[4]);
                __half2 p0 = __floats2half2_rn(w[1], w[2]);
                __half2 p1 = __floats2half2_rn(w[3], 0.f);
                __half2 q0 = __floats2half2_rn(w[5], w[6]);
                __half2 q1 = __floats2half2_rn(w[7], 0.f);
                uint4 pk;
                pk.x = *(unsigned*)&p0; pk.y = *(unsigned*)&p1;
                pk.z = *(unsigned*)&q0; pk.w = *(unsigned*)&q1;
                *(uint4*)(d_Yd + (vb * 64 + o0) * 4) = pk;
            }
        }
    }
}

// ---------------------------------------------------------------------------
// Stage 2: gather-combine. Block (32,8): tx = o-PAIR (channels 2tx,2tx+1),
// ty = v sub-lane. One LDG.128 per neighbor serves both channels; one
// LDS.128 fetches {j*32, wL, wE, wN}.
// ---------------------------------------------------------------------------
__global__ void __launch_bounds__(256) k_stage2(const float* __restrict__ Lw,
                                                const float* __restrict__ Ew,
                                                const float* __restrict__ Nw,
                                                const int*   __restrict__ nbr,
                                                const float* __restrict__ bias,
                                                float* __restrict__ out)
{
    __shared__ int   s_rj[32 * KK];
    __shared__ float s_rL[32 * KK], s_rE[32 * KK], s_rN[32 * KK];
    __shared__ int4  s_pk[32][KK];          // {j*32, wL, wE, wN}
    __shared__ int   s_cnt[32];
    __shared__ float tile[64][33];          // [o][vl]
    __shared__ float ss[8][32], sq[8][32];

    const int b     = blockIdx.y;
    const int vbase = blockIdx.x * 32;
    const int tx    = threadIdx.x;          // o-pair index (group index)
    const int ty    = threadIdx.y;          // v sub-lane; warp-uniform
    const int tid   = ty * 32 + tx;

    if (tid < 32 * KK) {
        int gidx = vbase * KK + tid;
        if (gidx < NVV * KK) {
            s_rj[tid] = nbr[gidx];
            s_rL[tid] = Lw[gidx]; s_rE[tid] = Ew[gidx]; s_rN[tid] = Nw[gidx];
        } else {
            s_rj[tid] = NVP;
        }
    }
    __syncthreads();
    if (tid < 32) {
        int c = 0;
#pragma unroll
        for (int k = 0; k < KK; k++) {
            int j = s_rj[tid * KK + k];
            if (j < NVP) {
                s_pk[tid][c] = make_int4(j * 32,
                                         __float_as_int(s_rL[tid * KK + k]),
                                         __float_as_int(s_rE[tid * KK + k]),
                                         __float_as_int(s_rN[tid * KK + k]));
                c++;
            }
        }
        s_cnt[tid] = c;
    }
    __syncthreads();

    const float* Y0b  = d_Y0 + (size_t)b * NVP * 64;
    const uint4* Ydb4 = (const uint4*)(d_Yd + (size_t)b * NVP * 256);  // 32 uint4 per v
    const float2 bo   = *(const float2*)(bias + tx * 2);
    float S = 0.f, Q = 0.f;

#pragma unroll
    for (int iter = 0; iter < 4; iter++) {
        int vl = iter * 8 + ty;
        int v  = vbase + vl;
        float acc0 = 0.f, acc1 = 0.f;
        if (v < NVV) {
            acc0 = bo.x; acc1 = bo.y;
            if (v < NVP) {
                float2 y0 = *(const float2*)(Y0b + v * 64 + tx * 2);
                acc0 += y0.x; acc1 += y0.y;
            }
            float aL0 = 0.f, aE0 = 0.f, aN0 = 0.f;
            float aL1 = 0.f, aE1 = 0.f, aN1 = 0.f;
            int cnt = s_cnt[vl];                  // warp-uniform
            for (int kk = 0; kk < cnt; kk++) {
                int4 pk = s_pk[vl][kk];           // LDS.128
                uint4 q = Ydb4[(size_t)(pk.x + tx)]; // LDG.128: both channels
                float wL = __int_as_float(pk.y);
                float wE = __int_as_float(pk.z);
                float wN = __int_as_float(pk.w);
                float2 f01 = __half22float2(*(__half2*)&q.x);
                float2 f23 = __half22float2(*(__half2*)&q.y);
                float2 g01 = __half22float2(*(__half2*)&q.z);
                float2 g23 = __half22float2(*(__half2*)&q.w);
                aL0 = fmaf(wL, f01.x, aL0);
                aE0 = fmaf(wE, f01.y, aE0);
                aN0 = fmaf(wN, f23.x, aN0);
                aL1 = fmaf(wL, g01.x, aL1);
                aE1 = fmaf(wE, g01.y, aE1);
                aN1 = fmaf(wN, g23.x, aN1);
            }
            acc0 += aL0 + aE0 + aN0;
            acc1 += aL1 + aE1 + aN1;
            S += acc0 + acc1;
            Q = fmaf(acc0, acc0, Q);
            Q = fmaf(acc1, acc1, Q);
        }
        tile[tx * 2 + 0][vl] = acc0;
        tile[tx * 2 + 1][vl] = acc1;
    }
    ss[ty][tx] = S;
    sq[ty][tx] = Q;
    __syncthreads();

    // Sector-friendly transposed write-out (unchanged from R8):
    // row = tid>>2, quad lane q = tid&3; float2 stores, 32B-covered sectors.
    {
        int r = tid >> 2;
        int q = tid & 3;
        size_t rowbase = (size_t)(b * 64 + r) * NVV;
#pragma unroll
        for (int u = 0; u < 4; u++) {
            int vl = q * 2 + u * 8;
            int v  = vbase + vl;
            if (v + 1 < NVV) {
                *(float2*)(out + rowbase + v) = make_float2(tile[r][vl], tile[r][vl + 1]);
            } else if (v < NVV) {
                out[rowbase + v] = tile[r][vl];
            }
        }
    }

    // Deterministic per-(b,group,vblk) partials. Group g == tx's channel pair.
    if (tid < 32) {
        float Sg = 0.f, Qg = 0.f;
#pragma unroll
        for (int yy = 0; yy < 8; yy++) {
            Sg += ss[yy][tid];
            Qg += sq[yy][tid];
        }
        d_psum[(b * 32 + tid) * VSTRIDE + blockIdx.x] = Sg;
        d_psq [(b * 32 + tid) * VSTRIDE + blockIdx.x] = Qg;
    }
}

// ---------------------------------------------------------------------------
// Stage 2.5: reduce partials (float4, fixed order) -> mean / rstd
// ---------------------------------------------------------------------------
__global__ void __launch_bounds__(256) k_reduce()
{
    __shared__ float sS[256], sQ[256];
    const int bg  = blockIdx.x;
    const int tid = threadIdx.x;
    const float4* P = (const float4*)(d_psum + (size_t)bg * VSTRIDE);
    const float4* R = (const float4*)(d_psq  + (size_t)bg * VSTRIDE);
    float S = 0.f, Q = 0.f;
    for (int i = tid; i < VSTRIDE / 4; i += 256) {
        float4 p = P[i];
        float4 r = R[i];
        S += (p.x + p.y) + (p.z + p.w);
        Q += (r.x + r.y) + (r.z + r.w);
    }
    sS[tid] = S; sQ[tid] = Q;
    __syncthreads();
    for (int st = 128; st > 0; st >>= 1) {
        if (tid < st) { sS[tid] += sS[tid + st]; sQ[tid] += sQ[tid + st]; }
        __syncthreads();
    }
    if (tid == 0) {
        float mean = sS[0] * (1.f / (float)GN_N);
        float var  = sQ[0] * (1.f / (float)GN_N) - mean * mean;
        d_mean[bg] = mean;
        d_rstd[bg] = rsqrtf(var + 1e-5f);
    }
}

// ---------------------------------------------------------------------------
// Stage 3: normalize + affine + ReLU, float4 over row-pairs. (unchanged)
// ---------------------------------------------------------------------------
#define S3_F4   20481
#define S3_PERT 8
__global__ void __launch_bounds__(256) k_stage3(float* __restrict__ out,
                                                const float* __restrict__ gamma,
                                                const float* __restrict__ beta)
{
    const int pr   = blockIdx.y;
    const int row0 = pr * 2;
    const int o0   = row0 & 63;
    const int o1   = o0 + 1;
    const int bgb  = (row0 >> 6) * 32;
    const float a0 = d_rstd[bgb + (o0 >> 1)] * gamma[o0];
    const float c0 = beta[o0] - d_mean[bgb + (o0 >> 1)] * a0;
    const float a1 = d_rstd[bgb + (o1 >> 1)] * gamma[o1];
    const float c1 = beta[o1] - d_mean[bgb + (o1 >> 1)] * a1;

    float4* base = (float4*)(out + (size_t)pr * 2 * NVV);
    int i0 = blockIdx.x * (256 * S3_PERT) + threadIdx.x;
#pragma unroll
    for (int u = 0; u < S3_PERT; u++) {
        int i4 = i0 + u * 256;
        if (i4 < S3_F4) {
            float4 t = base[i4];
            float ax, cx, az, cz;
            if (i4 < 10240)      { ax = a0; cx = c0; az = a0; cz = c0; }
            else if (i4 > 10240) { ax = a1; cx = c1; az = a1; cz = c1; }
            else                 { ax = a0; cx = c0; az = a1; cz = c1; }
            t.x = fmaxf(fmaf(t.x, ax, cx), 0.f);
            t.y = fmaxf(fmaf(t.y, ax, cx), 0.f);
            t.z = fmaxf(fmaf(t.z, az, cz), 0.f);
            t.w = fmaxf(fmaf(t.w, az, cz), 0.f);
            base[i4] = t;
        }
    }
}

// ---------------------------------------------------------------------------
extern "C" void kernel_launch(void* const* d_in, const int* in_sizes, int n_in,
                              void* d_out, int out_size)
{
    const float* x      = (const float*)d_in[0];
    const float* L_val  = (const float*)d_in[1];
    const float* EW_val = (const float*)d_in[2];
    const float* NS_val = (const float*)d_in[3];
    const float* coeffs = (const float*)d_in[4];
    const float* bias   = (const float*)d_in[5];
    const float* gamma  = (const float*)d_in[6];
    const float* beta   = (const float*)d_in[7];
    const int*   nbr    = (const int*)  d_in[8];
    float*       out    = (float*)d_out;

    static bool configured = false;
    if (!configured) {
        cudaFuncSetAttribute(k_stage1, cudaFuncAttributeMaxDynamicSharedMemorySize,
                             64 * (TM + 128) * (int)sizeof(float));
        configured = true;
    }

    // (1) Prep: coeffs transpose
    k_prep<<<64, 256>>>(coeffs);
    // (2,3) Stage 1 in two launches — keeps stage2 at ncu position 4
    {
        dim3 grid((NVP + TM - 1) / TM, 1, BB);          // (81, 1, 8) each
        size_t smem = 64 * (TM + 128) * sizeof(float);
        k_stage1<<<grid, 256, smem>>>(x, 0);
        k_stage1<<<grid, 256, smem>>>(x, 32);
    }
    // (4) Stage 2: gather-combine + pre-GN out + partials   <-- ncu position
    {
        dim3 grid(VBLKS, BB);                           // (1281, 8)
        dim3 block(32, 8);
        k_stage2<<<grid, block>>>(L_val, EW_val, NS_val, nbr, bias, out);
    }
    // (5) Stage 2.5: group statistics
    k_reduce<<<256, 256>>>();
    // (6) Stage 3: normalize + ReLU (in place), float4 over row-pairs
    {
        dim3 grid((S3_F4 + 256 * S3_PERT - 1) / (256 * S3_PERT), BB * CC / 2);
        k_stage3<<<grid, 256>>>(out, gamma, beta);
    }
}

// round 12
// speedup vs baseline: 1.4204x; 1.0315x over previous
#include <cuda_runtime.h>
#include <cuda_fp16.h>
#include <cstddef>

#define NVV   40962
#define NVP   10242
#define BB    8
#define CC    64
#define KK    7
#define VBLKS 1281              // ceil(40962/32)
#define VSTRIDE 1284            // padded to multiple of 4 (float4 reduce)
#define GN_N  (2*NVV)

#define TM 128                  // v per stage1 block

// Scratch (device globals — zero-initialized; no allocations allowed)
__device__ float  d_Y0[(size_t)BB * NVP * 64];        // up-proj  [b][v][o], 21 MB
__device__ __half d_Yd[(size_t)BB * NVP * 64 * 4];    // {y1,y2,y3,0} [b][v][o][4], 42 MB
__device__ float  d_S [(size_t)BB * NVV * 64];        // pre-GN [b][v][o], 84 MB
__device__ float  d_Bt[64 * 256];                     // coeffs transposed [i][o*4+s]
__device__ float  d_psum[256 * VSTRIDE];              // pad entries stay 0
__device__ float  d_psq [256 * VSTRIDE];
__device__ float  d_mean[256];
__device__ float  d_rstd[256];

#define FMA2(d, a, b, c) \
    asm("fma.rn.f32x2 %0, %1, %2, %3;" : "=l"(d) : "l"(a), "l"(b), "l"(c))

// ---------------------------------------------------------------------------
// Prep: transpose coeffs -> d_Bt[i][o*4+s]
// ---------------------------------------------------------------------------
__global__ void k_prep(const float* __restrict__ coeffs)
{
    int t = blockIdx.x * 256 + threadIdx.x;      // 16384 total
    int i = t >> 8;
    int r = t & 255;
    int o = r >> 2;
    int s = r & 3;
    d_Bt[i * 256 + r] = coeffs[(o * 64 + i) * 4 + s];
}

// ---------------------------------------------------------------------------
// Stage 1: y_s[b,v,o] = sum_i coeffs[o,i,s] * x[b,i,v]
// Packed f32x2 FMA, per-launch tile: 128 v x 32 o x 4 s. (unchanged)
// ---------------------------------------------------------------------------
__global__ void __launch_bounds__(256) k_stage1(const float* __restrict__ x,
                                                int obase)
{
    extern __shared__ float sm[];
    float* As = sm;              // [i][vl] : 64*128
    float* Bs = sm + 64 * TM;    // [i][ol*4+s] : 64*128

    const int b     = blockIdx.z;
    const int vbase = blockIdx.x * TM;
    const int tid   = threadIdx.x;

    for (int t = tid; t < 64 * 128; t += 256) {
        int i = t >> 7;
        int r = t & 127;
        Bs[t] = d_Bt[i * 256 + obase * 4 + r];
    }
    for (int t = tid; t < 64 * TM; t += 256) {
        int i  = t >> 7;
        int vl = t & 127;
        int v  = vbase + vl;
        As[t]  = (v < NVP) ? x[(b * 64 + i) * NVP + v] : 0.f;
    }
    __syncthreads();

    const int ol0   = (tid & 15) * 2;
    const int v_sub = (tid >> 4) * 8;

    unsigned long long acc[8][4];
#pragma unroll
    for (int a = 0; a < 8; a++)
#pragma unroll
        for (int c = 0; c < 4; c++) acc[a][c] = 0ULL;

#pragma unroll 4
    for (int i = 0; i < 64; i++) {
        const ulonglong2* Ap = (const ulonglong2*)(As + i * TM + v_sub);
        ulonglong2 a01 = Ap[0];
        ulonglong2 a23 = Ap[1];
        unsigned long long av[4] = {a01.x, a01.y, a23.x, a23.y};
        float4 b0 = *(const float4*)(Bs + i * 128 + ol0 * 4);
        float4 b1 = *(const float4*)(Bs + i * 128 + ol0 * 4 + 4);
        float bv[8] = {b0.x, b0.y, b0.z, b0.w, b1.x, b1.y, b1.z, b1.w};
#pragma unroll
        for (int a = 0; a < 8; a++) {
            unsigned bu = __float_as_uint(bv[a]);
            unsigned long long bb;
            asm("mov.b64 %0, {%1, %1};" : "=l"(bb) : "r"(bu));
#pragma unroll
            for (int c = 0; c < 4; c++)
                FMA2(acc[a][c], av[c], bb, acc[a][c]);
        }
    }

#pragma unroll
    for (int c = 0; c < 4; c++) {
#pragma unroll
        for (int par = 0; par < 2; par++) {
            int v = vbase + v_sub + c * 2 + par;
            if (v < NVP) {
                float w[8];
#pragma unroll
                for (int a = 0; a < 8; a++) {
                    unsigned long long u = acc[a][c];
                    w[a] = __uint_as_float(par ? (unsigned)(u >> 32)
                                               : (unsigned)(u & 0xffffffffULL));
                }
                size_t vb = (size_t)b * NVP + v;
                int o0 = obase + ol0;
                *(float2*)(d_Y0 + vb * 64 + o0) = make_float2(w[0], w[4]);
                __half2 p0 = __floats2half2_rn(w[1], w[2]);
                __half2 p1 = __floats2half2_rn(w[3], 0.f);
                __half2 q0 = __floats2half2_rn(w[5], w[6]);
                __half2 q1 = __floats2half2_rn(w[7], 0.f);
                uint4 pk;
                pk.x = *(unsigned*)&p0; pk.y = *(unsigned*)&p1;
                pk.z = *(unsigned*)&q0; pk.w = *(unsigned*)&q1;
                *(uint4*)(d_Yd + (vb * 64 + o0) * 4) = pk;
            }
        }
    }
}

// ---------------------------------------------------------------------------
// Stage 2: gather-combine. Block (32,8): tx = o-pair, ty = v sub-lane.
// One LDG.128 per hit serves both channels. NO smem tile: natural-layout
// float2 store to d_S[b][v][o] (warp: 256B contiguous, fully coalesced).
// ---------------------------------------------------------------------------
__global__ void __launch_bounds__(256) k_stage2(const float* __restrict__ Lw,
                                                const float* __restrict__ Ew,
                                                const float* __restrict__ Nw,
                                                const int*   __restrict__ nbr,
                                                const float* __restrict__ bias)
{
    __shared__ int   s_rj[32 * KK];
    __shared__ float s_rL[32 * KK], s_rE[32 * KK], s_rN[32 * KK];
    __shared__ int4  s_pk[32][KK];          // {j*32, wL, wE, wN}
    __shared__ int   s_cnt[32];
    __shared__ float ss[8][32], sq[8][32];

    const int b     = blockIdx.y;
    const int vbase = blockIdx.x * 32;
    const int tx    = threadIdx.x;          // o-pair index (= GN group)
    const int ty    = threadIdx.y;          // v sub-lane; warp-uniform
    const int tid   = ty * 32 + tx;

    if (tid < 32 * KK) {
        int gidx = vbase * KK + tid;
        if (gidx < NVV * KK) {
            s_rj[tid] = nbr[gidx];
            s_rL[tid] = Lw[gidx]; s_rE[tid] = Ew[gidx]; s_rN[tid] = Nw[gidx];
        } else {
            s_rj[tid] = NVP;
        }
    }
    __syncthreads();
    if (tid < 32) {
        int c = 0;
#pragma unroll
        for (int k = 0; k < KK; k++) {
            int j = s_rj[tid * KK + k];
            if (j < NVP) {
                s_pk[tid][c] = make_int4(j * 32,
                                         __float_as_int(s_rL[tid * KK + k]),
                                         __float_as_int(s_rE[tid * KK + k]),
                                         __float_as_int(s_rN[tid * KK + k]));
                c++;
            }
        }
        s_cnt[tid] = c;
    }
    __syncthreads();

    const float* Y0b  = d_Y0 + (size_t)b * NVP * 64;
    const uint4* Ydb4 = (const uint4*)(d_Yd + (size_t)b * NVP * 256);
    float*       Sb   = d_S  + (size_t)b * NVV * 64;
    const float2 bo   = *(const float2*)(bias + tx * 2);
    float S = 0.f, Q = 0.f;

#pragma unroll
    for (int iter = 0; iter < 4; iter++) {
        int vl = iter * 8 + ty;
        int v  = vbase + vl;
        if (v < NVV) {
            float acc0 = bo.x, acc1 = bo.y;
            if (v < NVP) {
                float2 y0 = *(const float2*)(Y0b + v * 64 + tx * 2);
                acc0 += y0.x; acc1 += y0.y;
            }
            float aL0 = 0.f, aE0 = 0.f, aN0 = 0.f;
            float aL1 = 0.f, aE1 = 0.f, aN1 = 0.f;
            int cnt = s_cnt[vl];                  // warp-uniform
            for (int kk = 0; kk < cnt; kk++) {
                int4 pk = s_pk[vl][kk];           // LDS.128 (broadcast)
                uint4 q = Ydb4[(size_t)(pk.x + tx)]; // LDG.128: both channels
                float wL = __int_as_float(pk.y);
                float wE = __int_as_float(pk.z);
                float wN = __int_as_float(pk.w);
                float2 f01 = __half22float2(*(__half2*)&q.x);
                float2 f23 = __half22float2(*(__half2*)&q.y);
                float2 g01 = __half22float2(*(__half2*)&q.z);
                float2 g23 = __half22float2(*(__half2*)&q.w);
                aL0 = fmaf(wL, f01.x, aL0);
                aE0 = fmaf(wE, f01.y, aE0);
                aN0 = fmaf(wN, f23.x, aN0);
                aL1 = fmaf(wL, g01.x, aL1);
                aE1 = fmaf(wE, g01.y, aE1);
                aN1 = fmaf(wN, g23.x, aN1);
            }
            acc0 += aL0 + aE0 + aN0;
            acc1 += aL1 + aE1 + aN1;
            S += acc0 + acc1;
            Q = fmaf(acc0, acc0, Q);
            Q = fmaf(acc1, acc1, Q);
            *(float2*)(Sb + (size_t)v * 64 + tx * 2) = make_float2(acc0, acc1);
        }
    }
    ss[ty][tx] = S;
    sq[ty][tx] = Q;
    __syncthreads();

    // Deterministic per-(b,group,vblk) partials. Group g == tx's channel pair.
    if (tid < 32) {
        float Sg = 0.f, Qg = 0.f;
#pragma unroll
        for (int yy = 0; yy < 8; yy++) {
            Sg += ss[yy][tid];
            Qg += sq[yy][tid];
        }
        d_psum[(b * 32 + tid) * VSTRIDE + blockIdx.x] = Sg;
        d_psq [(b * 32 + tid) * VSTRIDE + blockIdx.x] = Qg;
    }
}

// ---------------------------------------------------------------------------
// Stage 2.5: reduce partials (float4, fixed order) -> mean / rstd
// ---------------------------------------------------------------------------
__global__ void __launch_bounds__(256) k_reduce()
{
    __shared__ float sS[256], sQ[256];
    const int bg  = blockIdx.x;
    const int tid = threadIdx.x;
    const float4* P = (const float4*)(d_psum + (size_t)bg * VSTRIDE);
    const float4* R = (const float4*)(d_psq  + (size_t)bg * VSTRIDE);
    float S = 0.f, Q = 0.f;
    for (int i = tid; i < VSTRIDE / 4; i += 256) {
        float4 p = P[i];
        float4 r = R[i];
        S += (p.x + p.y) + (p.z + p.w);
        Q += (r.x + r.y) + (r.z + r.w);
    }
    sS[tid] = S; sQ[tid] = Q;
    __syncthreads();
    for (int st = 128; st > 0; st >>= 1) {
        if (tid < st) { sS[tid] += sS[tid + st]; sQ[tid] += sQ[tid + st]; }
        __syncthreads();
    }
    if (tid == 0) {
        float mean = sS[0] * (1.f / (float)GN_N);
        float var  = sQ[0] * (1.f / (float)GN_N) - mean * mean;
        d_mean[bg] = mean;
        d_rstd[bg] = rsqrtf(var + 1e-5f);
    }
}

// ---------------------------------------------------------------------------
// Stage 3: transpose [b][v][o] -> [b][o][v] + normalize + affine + ReLU.
// Block: (b, 64-vertex tile). Coalesced float4 loads, smem 64x65,
// sector-friendly float2 stores.
// ---------------------------------------------------------------------------
__global__ void __launch_bounds__(256) k_stage3(float* __restrict__ out,
                                                const float* __restrict__ gamma,
                                                const float* __restrict__ beta)
{
    __shared__ float s[64][65];

    const int b     = blockIdx.y;
    const int vbase = blockIdx.x * 64;
    const int t     = threadIdx.x;

    const float* Sb = d_S + (size_t)b * NVV * 64;

    // Load: 64 v-rows x 64 floats. Thread t handles float4 at (vl, o4).
#pragma unroll
    for (int p = 0; p < 4; p++) {
        int vl = p * 16 + (t >> 4);
        int o4 = (t & 15) * 4;
        int v  = vbase + vl;
        float4 val = make_float4(0.f, 0.f, 0.f, 0.f);
        if (v < NVV) val = *(const float4*)(Sb + (size_t)v * 64 + o4);
        s[vl][o4 + 0] = val.x;
        s[vl][o4 + 1] = val.y;
        s[vl][o4 + 2] = val.z;
        s[vl][o4 + 3] = val.w;
    }
    __syncthreads();

    // Write: thread t -> channel o = t>>2, quad q = t&3.
    const int o = t >> 2;
    const int q = t & 3;
    const int bg = b * 32 + (o >> 1);
    const float a = d_rstd[bg] * gamma[o];
    const float c = beta[o] - d_mean[bg] * a;
    size_t rowbase = (size_t)(b * 64 + o) * NVV;

#pragma unroll
    for (int u = 0; u < 8; u++) {
        int vl = q * 2 + u * 8;
        int v  = vbase + vl;
        if (v + 1 < NVV) {
            float2 w;
            w.x = fmaxf(fmaf(s[vl][o],     a, c), 0.f);
            w.y = fmaxf(fmaf(s[vl + 1][o], a, c), 0.f);
            *(float2*)(out + rowbase + v) = w;
        } else if (v < NVV) {
            out[rowbase + v] = fmaxf(fmaf(s[vl][o], a, c), 0.f);
        }
    }
}

// ---------------------------------------------------------------------------
extern "C" void kernel_launch(void* const* d_in, const int* in_sizes, int n_in,
                              void* d_out, int out_size)
{
    const float* x      = (const float*)d_in[0];
    const float* L_val  = (const float*)d_in[1];
    const float* EW_val = (const float*)d_in[2];
    const float* NS_val = (const float*)d_in[3];
    const float* coeffs = (const float*)d_in[4];
    const float* bias   = (const float*)d_in[5];
    const float* gamma  = (const float*)d_in[6];
    const float* beta   = (const float*)d_in[7];
    const int*   nbr    = (const int*)  d_in[8];
    float*       out    = (float*)d_out;

    static bool configured = false;
    if (!configured) {
        cudaFuncSetAttribute(k_stage1, cudaFuncAttributeMaxDynamicSharedMemorySize,
                             64 * (TM + 128) * (int)sizeof(float));
        configured = true;
    }

    // (1) Prep: coeffs transpose
    k_prep<<<64, 256>>>(coeffs);
    // (2,3) Stage 1 in two launches — keeps stage2 at ncu position 4
    {
        dim3 grid((NVP + TM - 1) / TM, 1, BB);          // (81, 1, 8) each
        size_t smem = 64 * (TM + 128) * sizeof(float);
        k_stage1<<<grid, 256, smem>>>(x, 0);
        k_stage1<<<grid, 256, smem>>>(x, 32);
    }
    // (4) Stage 2: gather-combine -> d_S + partials        <-- ncu position
    {
        dim3 grid(VBLKS, BB);                           // (1281, 8)
        dim3 block(32, 8);
        k_stage2<<<grid, block>>>(L_val, EW_val, NS_val, nbr, bias);
    }
    // (5) Stage 2.5: group statistics
    k_reduce<<<256, 256>>>();
    // (6) Stage 3: transpose + normalize + ReLU
    {
        dim3 grid((NVV + 63) / 64, BB);                 // (641, 8)
        k_stage3<<<grid, 256>>>(out, gamma, beta);
    }
}

// round 13
// speedup vs baseline: 1.4560x; 1.0250x over previous
#include <cuda_runtime.h>
#include <cuda_fp16.h>
#include <cstddef>

#define NVV   40962
#define NVP   10242
#define BB    8
#define CC    64
#define KK    7
#define VBLKS 1281              // ceil(40962/32)
#define GN_N  (2*NVV)

#define TM 128                  // v per stage1 block

// Scratch (device globals — zero-initialized; no allocations allowed)
__device__ float  d_Y0[(size_t)BB * NVP * 64];        // up-proj  [b][v][o], 21 MB
__device__ __half d_Yd[(size_t)BB * NVP * 64 * 4];    // {y1,y2,y3,0} [b][v][o][4], 42 MB
__device__ float  d_S [(size_t)BB * NVV * 64];        // pre-GN [b][v][o], 84 MB
__device__ float  d_Bt[64 * 256];                     // coeffs transposed [i][o*4+s]
__device__ float  d_psum[2 * VBLKS * 128];            // [half][vblk][(b&3)*32+g]
__device__ float  d_psq [2 * VBLKS * 128];
__device__ float  d_mean[256];
__device__ float  d_rstd[256];

#define FMA2(d, a, b, c) \
    asm("fma.rn.f32x2 %0, %1, %2, %3;" : "=l"(d) : "l"(a), "l"(b), "l"(c))

// ---------------------------------------------------------------------------
// Prep: transpose coeffs -> d_Bt[i][o*4+s]
// ---------------------------------------------------------------------------
__global__ void k_prep(const float* __restrict__ coeffs)
{
    int t = blockIdx.x * 256 + threadIdx.x;      // 16384 total
    int i = t >> 8;
    int r = t & 255;
    int o = r >> 2;
    int s = r & 3;
    d_Bt[i * 256 + r] = coeffs[(o * 64 + i) * 4 + s];
}

// ---------------------------------------------------------------------------
// Stage 1: y_s[b,v,o] = sum_i coeffs[o,i,s] * x[b,i,v]
// Packed f32x2 FMA, per-launch tile: 128 v x 32 o x 4 s. (unchanged)
// ---------------------------------------------------------------------------
__global__ void __launch_bounds__(256) k_stage1(const float* __restrict__ x,
                                                int obase)
{
    extern __shared__ float sm[];
    float* As = sm;              // [i][vl] : 64*128
    float* Bs = sm + 64 * TM;    // [i][ol*4+s] : 64*128

    const int b     = blockIdx.z;
    const int vbase = blockIdx.x * TM;
    const int tid   = threadIdx.x;

    for (int t = tid; t < 64 * 128; t += 256) {
        int i = t >> 7;
        int r = t & 127;
        Bs[t] = d_Bt[i * 256 + obase * 4 + r];
    }
    for (int t = tid; t < 64 * TM; t += 256) {
        int i  = t >> 7;
        int vl = t & 127;
        int v  = vbase + vl;
        As[t]  = (v < NVP) ? x[(b * 64 + i) * NVP + v] : 0.f;
    }
    __syncthreads();

    const int ol0   = (tid & 15) * 2;
    const int v_sub = (tid >> 4) * 8;

    unsigned long long acc[8][4];
#pragma unroll
    for (int a = 0; a < 8; a++)
#pragma unroll
        for (int c = 0; c < 4; c++) acc[a][c] = 0ULL;

#pragma unroll 4
    for (int i = 0; i < 64; i++) {
        const ulonglong2* Ap = (const ulonglong2*)(As + i * TM + v_sub);
        ulonglong2 a01 = Ap[0];
        ulonglong2 a23 = Ap[1];
        unsigned long long av[4] = {a01.x, a01.y, a23.x, a23.y};
        float4 b0 = *(const float4*)(Bs + i * 128 + ol0 * 4);
        float4 b1 = *(const float4*)(Bs + i * 128 + ol0 * 4 + 4);
        float bv[8] = {b0.x, b0.y, b0.z, b0.w, b1.x, b1.y, b1.z, b1.w};
#pragma unroll
        for (int a = 0; a < 8; a++) {
            unsigned bu = __float_as_uint(bv[a]);
            unsigned long long bb;
            asm("mov.b64 %0, {%1, %1};" : "=l"(bb) : "r"(bu));
#pragma unroll
            for (int c = 0; c < 4; c++)
                FMA2(acc[a][c], av[c], bb, acc[a][c]);
        }
    }

#pragma unroll
    for (int c = 0; c < 4; c++) {
#pragma unroll
        for (int par = 0; par < 2; par++) {
            int v = vbase + v_sub + c * 2 + par;
            if (v < NVP) {
                float w[8];
#pragma unroll
                for (int a = 0; a < 8; a++) {
                    unsigned long long u = acc[a][c];
                    w[a] = __uint_as_float(par ? (unsigned)(u >> 32)
                                               : (unsigned)(u & 0xffffffffULL));
                }
                size_t vb = (size_t)b * NVP + v;
                int o0 = obase + ol0;
                *(float2*)(d_Y0 + vb * 64 + o0) = make_float2(w[0], w[4]);
                __half2 p0 = __floats2half2_rn(w[1], w[2]);
                __half2 p1 = __floats2half2_rn(w[3], 0.f);
                __half2 q0 = __floats2half2_rn(w[5], w[6]);
                __half2 q1 = __floats2half2_rn(w[7], 0.f);
                uint4 pk;
                pk.x = *(unsigned*)&p0; pk.y = *(unsigned*)&p1;
                pk.z = *(unsigned*)&q0; pk.w = *(unsigned*)&q1;
                *(uint4*)(d_Yd + (vb * 64 + o0) * 4) = pk;
            }
        }
    }
}

// ---------------------------------------------------------------------------
// Stage 2: gather-combine, 4 BATCHES per block (ty = batch sub-index).
// Neighbor load + compaction done ONCE per 32-vertex tile for 4 batches.
// tx = o-pair; each thread sweeps all 32 vertices of its batch.
// ---------------------------------------------------------------------------
__global__ void __launch_bounds__(128) k_stage2(const float* __restrict__ Lw,
                                                const float* __restrict__ Ew,
                                                const float* __restrict__ Nw,
                                                const int*   __restrict__ nbr,
                                                const float* __restrict__ bias)
{
    __shared__ int   s_rj[32 * KK];
    __shared__ float s_rL[32 * KK], s_rE[32 * KK], s_rN[32 * KK];
    __shared__ int4  s_pk[32][KK];          // {j*32, wL, wE, wN}
    __shared__ int   s_cnt[32];

    const int vbase = blockIdx.x * 32;
    const int half  = blockIdx.y;           // batches [half*4, half*4+4)
    const int tx    = threadIdx.x;          // o-pair index (= GN group)
    const int ty    = threadIdx.y;          // batch sub-index
    const int tid   = ty * 32 + tx;
    const int b     = half * 4 + ty;

    for (int t = tid; t < 32 * KK; t += 128) {
        int gidx = vbase * KK + t;
        if (gidx < NVV * KK) {
            s_rj[t] = nbr[gidx];
            s_rL[t] = Lw[gidx]; s_rE[t] = Ew[gidx]; s_rN[t] = Nw[gidx];
        } else {
            s_rj[t] = NVP;
        }
    }
    __syncthreads();
    if (tid < 32) {
        int c = 0;
#pragma unroll
        for (int k = 0; k < KK; k++) {
            int j = s_rj[tid * KK + k];
            if (j < NVP) {
                s_pk[tid][c] = make_int4(j * 32,
                                         __float_as_int(s_rL[tid * KK + k]),
                                         __float_as_int(s_rE[tid * KK + k]),
                                         __float_as_int(s_rN[tid * KK + k]));
                c++;
            }
        }
        s_cnt[tid] = c;
    }
    __syncthreads();

    const float* Y0b  = d_Y0 + (size_t)b * NVP * 64;
    const uint4* Ydb4 = (const uint4*)d_Yd + (size_t)b * NVP * 32;
    float*       Sb   = d_S  + (size_t)b * NVV * 64;
    const float2 bo   = *(const float2*)(bias + tx * 2);
    float S = 0.f, Q = 0.f;

    int vmax = NVV - vbase; if (vmax > 32) vmax = 32;   // block-uniform
    for (int vl = 0; vl < vmax; vl++) {
        int v = vbase + vl;
        float acc0 = bo.x, acc1 = bo.y;
        if (v < NVP) {                            // warp-uniform
            float2 y0 = *(const float2*)(Y0b + v * 64 + tx * 2);
            acc0 += y0.x; acc1 += y0.y;
        }
        float aL0 = 0.f, aE0 = 0.f, aN0 = 0.f;
        float aL1 = 0.f, aE1 = 0.f, aN1 = 0.f;
        int cnt = s_cnt[vl];                      // warp-uniform
        for (int kk = 0; kk < cnt; kk++) {
            int4 pk = s_pk[vl][kk];               // LDS.128 (broadcast)
            uint4 q = Ydb4[(size_t)(pk.x + tx)];  // LDG.128: both channels
            float wL = __int_as_float(pk.y);
            float wE = __int_as_float(pk.z);
            float wN = __int_as_float(pk.w);
            float2 f01 = __half22float2(*(__half2*)&q.x);
            float2 f23 = __half22float2(*(__half2*)&q.y);
            float2 g01 = __half22float2(*(__half2*)&q.z);
            float2 g23 = __half22float2(*(__half2*)&q.w);
            aL0 = fmaf(wL, f01.x, aL0);
            aE0 = fmaf(wE, f01.y, aE0);
            aN0 = fmaf(wN, f23.x, aN0);
            aL1 = fmaf(wL, g01.x, aL1);
            aE1 = fmaf(wE, g01.y, aE1);
            aN1 = fmaf(wN, g23.x, aN1);
        }
        acc0 += aL0 + aE0 + aN0;
        acc1 += aL1 + aE1 + aN1;
        S += acc0 + acc1;
        Q = fmaf(acc0, acc0, Q);
        Q = fmaf(acc1, acc1, Q);
        *(float2*)(Sb + (size_t)v * 64 + tx * 2) = make_float2(acc0, acc1);
    }

    // Contiguous partial store: 512B per block
    size_t pidx = ((size_t)half * VBLKS + blockIdx.x) * 128 + tid;
    d_psum[pidx] = S;
    d_psq [pidx] = Q;
}

// ---------------------------------------------------------------------------
// Stage 2.5: reduce partials -> mean / rstd per (b, group). Fixed-order.
// bg = b*32+g ; b = half*4+ty ; slot within block row = ty*32+g.
// ---------------------------------------------------------------------------
__global__ void __launch_bounds__(256) k_reduce()
{
    __shared__ float sS[256], sQ[256];
    const int bg   = blockIdx.x;
    const int tid  = threadIdx.x;
    const int bb   = bg >> 5;
    const int g    = bg & 31;
    const int half = bb >> 2;
    const int tloc = (bb & 3) * 32 + g;
    const float* P = d_psum + (size_t)half * VBLKS * 128 + tloc;
    const float* R = d_psq  + (size_t)half * VBLKS * 128 + tloc;
    float S = 0.f, Q = 0.f;
    for (int i = tid; i < VBLKS; i += 256) {
        S += P[(size_t)i * 128];
        Q += R[(size_t)i * 128];
    }
    sS[tid] = S; sQ[tid] = Q;
    __syncthreads();
    for (int st = 128; st > 0; st >>= 1) {
        if (tid < st) { sS[tid] += sS[tid + st]; sQ[tid] += sQ[tid + st]; }
        __syncthreads();
    }
    if (tid == 0) {
        float mean = sS[0] * (1.f / (float)GN_N);
        float var  = sQ[0] * (1.f / (float)GN_N) - mean * mean;
        d_mean[bg] = mean;
        d_rstd[bg] = rsqrtf(var + 1e-5f);
    }
}

// ---------------------------------------------------------------------------
// Stage 3: transpose [b][v][o] -> [b][o][v] + normalize + affine + ReLU.
// (unchanged from R12)
// ---------------------------------------------------------------------------
__global__ void __launch_bounds__(256) k_stage3(float* __restrict__ out,
                                                const float* __restrict__ gamma,
                                                const float* __restrict__ beta)
{
    __shared__ float s[64][65];

    const int b     = blockIdx.y;
    const int vbase = blockIdx.x * 64;
    const int t     = threadIdx.x;

    const float* Sb = d_S + (size_t)b * NVV * 64;

#pragma unroll
    for (int p = 0; p < 4; p++) {
        int vl = p * 16 + (t >> 4);
        int o4 = (t & 15) * 4;
        int v  = vbase + vl;
        float4 val = make_float4(0.f, 0.f, 0.f, 0.f);
        if (v < NVV) val = *(const float4*)(Sb + (size_t)v * 64 + o4);
        s[vl][o4 + 0] = val.x;
        s[vl][o4 + 1] = val.y;
        s[vl][o4 + 2] = val.z;
        s[vl][o4 + 3] = val.w;
    }
    __syncthreads();

    const int o = t >> 2;
    const int q = t & 3;
    const int bg = b * 32 + (o >> 1);
    const float a = d_rstd[bg] * gamma[o];
    const float c = beta[o] - d_mean[bg] * a;
    size_t rowbase = (size_t)(b * 64 + o) * NVV;

#pragma unroll
    for (int u = 0; u < 8; u++) {
        int vl = q * 2 + u * 8;
        int v  = vbase + vl;
        if (v + 1 < NVV) {
            float2 w;
            w.x = fmaxf(fmaf(s[vl][o],     a, c), 0.f);
            w.y = fmaxf(fmaf(s[vl + 1][o], a, c), 0.f);
            *(float2*)(out + rowbase + v) = w;
        } else if (v < NVV) {
            out[rowbase + v] = fmaxf(fmaf(s[vl][o], a, c), 0.f);
        }
    }
}

// ---------------------------------------------------------------------------
extern "C" void kernel_launch(void* const* d_in, const int* in_sizes, int n_in,
                              void* d_out, int out_size)
{
    const float* x      = (const float*)d_in[0];
    const float* L_val  = (const float*)d_in[1];
    const float* EW_val = (const float*)d_in[2];
    const float* NS_val = (const float*)d_in[3];
    const float* coeffs = (const float*)d_in[4];
    const float* bias   = (const float*)d_in[5];
    const float* gamma  = (const float*)d_in[6];
    const float* beta   = (const float*)d_in[7];
    const int*   nbr    = (const int*)  d_in[8];
    float*       out    = (float*)d_out;

    static bool configured = false;
    if (!configured) {
        cudaFuncSetAttribute(k_stage1, cudaFuncAttributeMaxDynamicSharedMemorySize,
                             64 * (TM + 128) * (int)sizeof(float));
        configured = true;
    }

    // (1) Prep: coeffs transpose
    k_prep<<<64, 256>>>(coeffs);
    // (2,3) Stage 1 in two launches — keeps stage2 at ncu position 4
    {
        dim3 grid((NVP + TM - 1) / TM, 1, BB);          // (81, 1, 8) each
        size_t smem = 64 * (TM + 128) * sizeof(float);
        k_stage1<<<grid, 256, smem>>>(x, 0);
        k_stage1<<<grid, 256, smem>>>(x, 32);
    }
    // (4) Stage 2: gather-combine -> d_S + partials        <-- ncu position
    {
        dim3 grid(VBLKS, 2);                            // (1281, 2)
        dim3 block(32, 4);
        k_stage2<<<grid, block>>>(L_val, EW_val, NS_val, nbr, bias);
    }
    // (5) Stage 2.5: group statistics
    k_reduce<<<256, 256>>>();
    // (6) Stage 3: transpose + normalize + ReLU
    {
        dim3 grid((NVV + 63) / 64, BB);                 // (641, 8)
        k_stage3<<<grid, 256>>>(out, gamma, beta);
    }
}